// round 16
// baseline (speedup 1.0000x reference)
#include <cuda_runtime.h>
#include <cstdint>

// Problem shape (fixed by the dataset)
#define B_BATCH 4
#define E_EDGES 320000
#define N_NODES 10000
#define F_FEAT  64

// Decomposition
#define RANGES   16
#define RNODES   (N_NODES / RANGES)     // 625 nodes per range
#define CHUNKS   5
#define WEDGES   (E_EDGES / CHUNKS)     // 64000 edges per chunk
#define SUB      2000                   // edges per subchunk
#define NSUB     (WEDGES / SUB)         // 32
#define THREADS  256                    // 8 warps
#define QCAP     96                     // queue capacity (lambda ~15.6)

// smem layout (bytes)
#define ACC_BYTES  (RNODES * F_FEAT * 4)            // 160000
#define IDX_BYTES  (SUB * 4)                        // 8000 per buffer
#define OFF_IDX    ACC_BYTES                        // two idx buffers
#define OFF_Q      (OFF_IDX + 2 * IDX_BYTES)        // 176000
#define OFF_QN     (OFF_Q + 8 * QCAP * 2)           // 177536
#define SMEM_BYTES (OFF_QN + 64)                    // 177600

// Node-range aggregation scatter-add.
// Each CTA owns (range, chunk, batch): accumulates its chunk's edges whose
// node falls in its 625-node range into a 160KB smem accumulator, then
// flushes once with RED. Cuts L2 RMW ops 6.4x vs direct scatter (the
// measured ~70us plateau across RED and TMA-reduce implementations).
__global__ __launch_bounds__(THREADS, 1) void range_agg_kernel(
    const float2* __restrict__ msgf2,  // [B*E, 32] float2
    const int*    __restrict__ idx,    // [B*E]
    float*        __restrict__ out)    // [B, N, 64]
{
    extern __shared__ __align__(16) char sm[];
    float*          acc  = reinterpret_cast<float*>(sm);
    unsigned short* qbuf = reinterpret_cast<unsigned short*>(sm + OFF_Q);
    int*            qn   = reinterpret_cast<int*>(sm + OFF_QN);

    const int r = blockIdx.x, c = blockIdx.y, b = blockIdx.z;
    const int nbase = r * RNODES;
    const long long ebase = (long long)b * E_EDGES + (long long)c * WEDGES;

    const int tid  = threadIdx.x;
    const int warp = tid >> 5;
    const int lane = tid & 31;

    // zero accumulator (10000 float4)
    const float4 z4 = make_float4(0.f, 0.f, 0.f, 0.f);
    for (int i = tid; i < RNODES * 16; i += THREADS)
        reinterpret_cast<float4*>(acc)[i] = z4;
    if (tid < 8) qn[tid] = 0;

    // stage subchunk 0 indices into buffer 0
    int4* sidx4_0 = reinterpret_cast<int4*>(sm + OFF_IDX);
    for (int i = tid; i < SUB / 4; i += THREADS)
        sidx4_0[i] = __ldg(reinterpret_cast<const int4*>(idx + ebase) + i);
    __syncthreads();

    for (int s = 0; s < NSUB; ++s) {
        const int buf = s & 1;
        const int*  sidx  = reinterpret_cast<const int*>(sm + OFF_IDX + buf * IDX_BYTES);
        const int4* sidx4 = reinterpret_cast<const int4*>(sidx);
        const long long sbase = ebase + (long long)s * SUB;

        // prefetch next subchunk's indices into the other buffer
        if (s + 1 < NSUB) {
            int4* nxt = reinterpret_cast<int4*>(sm + OFF_IDX + (buf ^ 1) * IDX_BYTES);
            const int4* g = reinterpret_cast<const int4*>(idx + ebase + (long long)(s + 1) * SUB);
            for (int i = tid; i < SUB / 4; i += THREADS)
                nxt[i] = __ldg(g + i);
        }

        // classify: push in-range edges to the owner warp's queue
        for (int i = tid; i < SUB / 4; i += THREADS) {
            const int4 v = sidx4[i];
            const int nodes[4] = { v.x, v.y, v.z, v.w };
#pragma unroll
            for (int k = 0; k < 4; ++k) {
                const int nl = nodes[k] - nbase;
                if ((unsigned)nl < (unsigned)RNODES) {
                    const int w = nl & 7;
                    const int p = atomicAdd(&qn[w], 1);
                    if (p < QCAP) {
                        qbuf[w * QCAP + p] = (unsigned short)(i * 4 + k);
                    } else {
                        // spill (statistically never): direct atomic accumulate
                        const float* m = reinterpret_cast<const float*>(
                            msgf2 + (sbase + i * 4 + k) * 32);
                        float* a = acc + nl * F_FEAT;
                        for (int t2 = 0; t2 < F_FEAT; ++t2)
                            atomicAdd(a + t2, m[t2]);
                    }
                }
            }
        }
        __syncthreads();

        // drain own queue: 8 outstanding 256B reads per warp
        const int n = min(qn[warp], QCAP);
        const unsigned short* myq = qbuf + warp * QCAP;
        int p = 0;
        while (p < n) {
            const int m = min(8, n - p);
            float2 v[8];
            int    loc[8];
#pragma unroll
            for (int i = 0; i < 8; ++i) {
                if (i < m) {
                    const int e = myq[p + i];
                    loc[i] = sidx[e] - nbase;
                    v[i]   = __ldcs(msgf2 + (sbase + e) * 32 + lane);
                }
            }
#pragma unroll
            for (int i = 0; i < 8; ++i) {
                if (i < m) {
                    float2* a = reinterpret_cast<float2*>(acc) + loc[i] * 32 + lane;
                    float2 t = *a;
                    t.x += v[i].x; t.y += v[i].y;
                    *a = t;
                }
            }
            p += m;
        }
        if (lane == 0) qn[warp] = 0;   // reset for next subchunk (pre-sync)
        __syncthreads();
    }

    // flush: 625 nodes x 16 float4, one RED.v4 each (5 chunk-CTAs sum per node)
    const int f4 = tid & 15;
    for (int i = tid >> 4; i < RNODES; i += 16) {
        const float4 vv = reinterpret_cast<const float4*>(acc)[i * 16 + f4];
        float* dst = out + ((long long)b * N_NODES + nbase + i) * F_FEAT + f4 * 4;
        asm volatile(
            "red.global.add.v4.f32 [%0], {%1, %2, %3, %4};"
            :: "l"(dst), "f"(vv.x), "f"(vv.y), "f"(vv.z), "f"(vv.w)
            : "memory");
    }
}

extern "C" void kernel_launch(void* const* d_in, const int* in_sizes, int n_in,
                              void* d_out, int out_size) {
    const float2* msg = (const float2*)d_in[0];   // msg_vectors [B,E,F] f32
    const int*    idx = (const int*)d_in[1];      // start_indices [B,E] i32
    // d_in[2] = h_v, unused by the reference computation
    float* out = (float*)d_out;                   // [B,N,F] f32

    static bool attr_set = false;
    if (!attr_set) {
        cudaFuncSetAttribute(range_agg_kernel,
                             cudaFuncAttributeMaxDynamicSharedMemorySize, SMEM_BYTES);
        attr_set = true;
    }

    // 1) zero the output (flush uses RED; harness poisons with 0xAA)
    cudaMemsetAsync(out, 0, (size_t)out_size * sizeof(float), 0);

    // 2) node-range aggregation: grid = (ranges, chunks, batches)
    dim3 grid(RANGES, CHUNKS, B_BATCH);           // 320 CTAs, 1 per SM
    range_agg_kernel<<<grid, THREADS, SMEM_BYTES>>>(msg, idx, out);
}

// round 17
// speedup vs baseline: 5.0277x; 5.0277x over previous
#include <cuda_runtime.h>
#include <cstdint>

// Problem shape (fixed by the dataset)
#define B_BATCH 4
#define E_EDGES 320000
#define N_NODES 10000
#define F_FEAT  64
#define NBINS   (B_BATCH * N_NODES)    // 40000
#define CAP     64                     // bucket capacity (lambda = 32)
#define OVF_MAX 32768

// Scratch (allocation-free: __device__ globals)
__device__ int d_cnt[NBINS];
__device__ int d_bucket[NBINS * CAP];  // 10.24 MB, L2-resident
__device__ int d_ovf_cnt;
__device__ int d_ovf[OVF_MAX];

// ---------------------------------------------------------------- K0: reset
__global__ __launch_bounds__(256) void reset_kernel() {
    int i = blockIdx.x * blockDim.x + threadIdx.x;
    if (i < NBINS) d_cnt[i] = 0;
    if (i == 0)    d_ovf_cnt = 0;
}

// ---------------------------------------------------------------- K1: fill
// 4 edges per thread (int4 idx loads). Counters + bucket are L2-resident.
__global__ __launch_bounds__(256) void fill_kernel(const int* __restrict__ start_idx) {
    const int b  = blockIdx.y;
    const int e0 = (blockIdx.x * blockDim.x + threadIdx.x) * 4;
    if (e0 >= E_EDGES) return;

    const int4 v = __ldg(reinterpret_cast<const int4*>(start_idx + b * E_EDGES + e0));
    const int node[4] = { v.x, v.y, v.z, v.w };
#pragma unroll
    for (int k = 0; k < 4; ++k) {
        const int bn   = b * N_NODES + node[k];
        const int slot = atomicAdd(&d_cnt[bn], 1);
        if (slot < CAP) {
            d_bucket[bn * CAP + slot] = e0 + k;
        } else {
            int p = atomicAdd(&d_ovf_cnt, 1);
            if (p < OVF_MAX) d_ovf[p] = b * E_EDGES + e0 + k;
        }
    }
}

// ---------------------------------------------------------------- K2: gather
// One full warp per (b,node); lane owns one float2 of the 64 features.
// Per iteration: 2 uniform LDG.128 broadcast 8 edge ids, then 8 edges' 256B
// msg reads are all in flight (MLP 8/lane) before accumulation. One coalesced
// 256B store per node -> out needs NO zero-init and NO RMW traffic.
__global__ __launch_bounds__(256) void gather_kernel(
    const float2* __restrict__ msgf2,  // [B*E, 32] float2
    float2*       __restrict__ outf2)  // [B*N, 32] float2
{
    const int bn = blockIdx.x * 8 + (threadIdx.x >> 5);   // (b,node) bin
    const int lane = threadIdx.x & 31;
    if (bn >= NBINS) return;

    const int b = bn / N_NODES;
    const long long mbase = (long long)b * E_EDGES;
    const int cnt = min(d_cnt[bn], CAP);
    const int* gq = d_bucket + bn * CAP;

    float accx = 0.f, accy = 0.f;

    const int cnt8 = cnt & ~7;
    for (int j = 0; j < cnt8; j += 8) {
        const int4 ia = __ldg(reinterpret_cast<const int4*>(gq + j));
        const int4 ib = __ldg(reinterpret_cast<const int4*>(gq + j + 4));
        const int ids[8] = { ia.x, ia.y, ia.z, ia.w, ib.x, ib.y, ib.z, ib.w };

        float2 v[8];
#pragma unroll
        for (int i = 0; i < 8; ++i)
            v[i] = __ldcs(msgf2 + (mbase + ids[i]) * 32 + lane);

#pragma unroll
        for (int i = 0; i < 8; ++i) { accx += v[i].x; accy += v[i].y; }
    }
    for (int j = cnt8; j < cnt; ++j) {
        const float2 v = __ldcs(msgf2 + (mbase + __ldg(gq + j)) * 32 + lane);
        accx += v.x; accy += v.y;
    }

    outf2[(long long)bn * 32 + lane] = make_float2(accx, accy);
}

// ---------------------------------------------------------------- K3: overflow
// RED-adds (statistically ~never) edges that overflowed their bucket, after
// gather's plain stores.
__global__ __launch_bounds__(256) void overflow_kernel(
    const float4* __restrict__ msg,
    const int*    __restrict__ start_idx,
    float*        __restrict__ out)
{
    const int total = min(d_ovf_cnt, OVF_MAX);
    for (int i = blockIdx.x * blockDim.x + threadIdx.x; i < total;
         i += gridDim.x * blockDim.x) {
        const int be   = d_ovf[i];
        const int b    = be / E_EDGES;
        const int node = __ldg(start_idx + be);
        const float4* m = msg + (long long)be * 16;
        float* dst = out + ((long long)b * N_NODES + node) * F_FEAT;
#pragma unroll
        for (int f4 = 0; f4 < 16; ++f4) {
            const float4 v = m[f4];
            asm volatile(
                "red.global.add.v4.f32 [%0], {%1, %2, %3, %4};"
                :: "l"(dst + f4 * 4), "f"(v.x), "f"(v.y), "f"(v.z), "f"(v.w)
                : "memory");
        }
    }
}

extern "C" void kernel_launch(void* const* d_in, const int* in_sizes, int n_in,
                              void* d_out, int out_size) {
    const float2* msg2 = (const float2*)d_in[0];  // msg_vectors [B,E,F] f32
    const float4* msg4 = (const float4*)d_in[0];
    const int*    idx  = (const int*)d_in[1];     // start_indices [B,E] i32
    // d_in[2] = h_v, unused by the reference computation
    float* out = (float*)d_out;                   // [B,N,F] f32

    // K0: reset counters
    reset_kernel<<<(NBINS + 255) / 256, 256>>>();

    // K1: bin edges (4 per thread)
    dim3 fgrid((E_EDGES / 4 + 255) / 256, B_BATCH);   // (313, 4)
    fill_kernel<<<fgrid, 256>>>(idx);

    // K2: warp-per-node gather; writes every output element (no memset needed)
    gather_kernel<<<NBINS / 8, 256>>>(msg2, (float2*)out);

    // K3: fold in (rare) overflow edges
    overflow_kernel<<<8, 256>>>(msg4, idx, out);
}